// round 1
// baseline (speedup 1.0000x reference)
#include <cuda_runtime.h>
#include <cuda_bf16.h>

// Problem constants (from reference setup_inputs): T=256, BS=128, N=2048.
#define T_STEPS 256
#define BSZ     128
#define NFEAT   2048
#define BLOCK   256
#define EPT     (NFEAT / BLOCK)   // 8 elements per thread
#define NWARP   (BLOCK / 32)      // 8 warps
#define FUDGE_C 1e-4f

__global__ __launch_bounds__(BLOCK, 1)
void elbo_scan_kernel(const float* __restrict__ noises,   // [T,BS]
                      const float* __restrict__ ys,       // [T,BS]
                      const float* __restrict__ qs,       // [T,BS]
                      const float* __restrict__ z_biases, // [N]
                      const float* __restrict__ w_in,     // [N]
                      const float* __restrict__ w_inq,    // [N]
                      const float* __restrict__ p_llr,
                      const float* __restrict__ p_llrd,
                      const float* __restrict__ p_sigb,
                      const float* __restrict__ p_os,
                      const float* __restrict__ p_ufs,
                      const float* __restrict__ p_spwd,
                      const float* __restrict__ p_qsc,
                      const float* __restrict__ p_tq,
                      const float* __restrict__ p_ty,
                      const float* __restrict__ p_te,
                      float* __restrict__ out)            // [T,BS]
{
    const int b    = blockIdx.x;       // batch lane
    const int tid  = threadIdx.x;
    const int wid  = tid >> 5;
    const int lane = tid & 31;

    __shared__ float s_y[T_STEPS];
    __shared__ float s_n[T_STEPS];
    __shared__ float s_q[T_STEPS];
    __shared__ float s_pu[2][NWARP];   // double-buffered partials: dot(w_out,h)
    __shared__ float s_ph[2][NWARP];   // double-buffered partials: sum(h^2)

    // Stage this lane's input columns into SMEM (one time; T_STEPS == BLOCK).
    s_y[tid] = ys[tid * BSZ + b];
    s_n[tid] = noises[tid * BSZ + b];
    s_q[tid] = qs[tid * BSZ + b];

    // Derived scalar parameters (replicated per thread; broadcast LDGs, one time).
    const float lr0  = expf(p_llr[0]);
    const float lrd  = expf(p_llrd[0]);
    const float sigb = p_sigb[0];
    const float osc  = p_os[0];
    const float ufs  = p_ufs[0];
    const float spwd = log1pf(expf(p_spwd[0]));         // softplus
    const float qsc  = p_qsc[0];
    const float tq   = 1.0f + log1pf(expf(p_tq[0]));
    const float ty   = 1.0f + log1pf(expf(p_ty[0]));
    const float te   = 1.0f + log1pf(expf(p_te[0]));
    const float itq = 1.0f / tq, ctq = 1.0f - itq;
    const float ity = 1.0f / ty, cty = 1.0f - ity;
    const float ite = 1.0f / te, cte = 1.0f - ite;

    // Per-thread slices (all register resident).
    float win[EPT], wiq[EPT], bia[EPT], wout[EPT], h[EPT];
    {
        const int base = tid * EPT;
        const float4* w4 = reinterpret_cast<const float4*>(w_in + base);
        const float4* q4 = reinterpret_cast<const float4*>(w_inq + base);
        const float4* z4 = reinterpret_cast<const float4*>(z_biases + base);
        #pragma unroll
        for (int v = 0; v < EPT / 4; ++v) {
            float4 a = w4[v], c = q4[v], z = z4[v];
            win[4*v+0] = a.x; win[4*v+1] = a.y; win[4*v+2] = a.z; win[4*v+3] = a.w;
            wiq[4*v+0] = c.x; wiq[4*v+1] = c.y; wiq[4*v+2] = c.z; wiq[4*v+3] = c.w;
            bia[4*v+0] = sigb * z.x; bia[4*v+1] = sigb * z.y;
            bia[4*v+2] = sigb * z.z; bia[4*v+3] = sigb * z.w;
        }
    }
    #pragma unroll
    for (int k = 0; k < EPT; ++k) { wout[k] = 0.0f; h[k] = 0.0f; }

    __syncthreads();   // SMEM columns ready

    // Replicated scalar state (identical deterministic values in every thread,
    // so no broadcast barrier is needed per step).
    float lrmult = 1.0f, ylp = 0.0f, elp = 0.0f;
    float qlp   = s_q[0] * itq;            // qlp_0 = q_0 / tq
    float x     = s_n[0];                  // x_0 = 0*ufs + 0 + noise_0
    float cq    = qsc * qlp;
    float lrelp = 0.0f, wdec = 1.0f;       // deferred w_out update (identity at t=0)

    for (int t = 0; t < T_STEPS; ++t) {
        // Phase 1: apply deferred w_out update from step t-1, compute h_t,
        // accumulate dot(w_out,h) and sum(h^2). All register-local.
        float au = 0.0f, ah = 0.0f;
        #pragma unroll
        for (int k = 0; k < EPT; ++k) {
            float wv = fmaf(lrelp, h[k], wout[k] * wdec);
            wout[k] = wv;
            float hv = fmaf(win[k], x, fmaf(wiq[k], cq, bia[k]));
            hv = fmaxf(hv, 0.0f);
            h[k] = hv;
            au = fmaf(wv, hv, au);
            ah = fmaf(hv, hv, ah);
        }

        // Warp butterfly reduction (two independent chains interleaved).
        #pragma unroll
        for (int off = 16; off; off >>= 1) {
            au += __shfl_xor_sync(0xFFFFFFFFu, au, off);
            ah += __shfl_xor_sync(0xFFFFFFFFu, ah, off);
        }
        const int buf = t & 1;
        if (lane == 0) { s_pu[buf][wid] = au; s_ph[buf][wid] = ah; }
        __syncthreads();   // the ONLY barrier per step

        // Every thread redundantly combines partials and runs the scalar chain.
        float un = 0.0f, h2 = 0.0f;
        #pragma unroll
        for (int w = 0; w < NWARP; ++w) { un += s_pu[buf][w]; h2 += s_ph[buf][w]; }

        if (tid == 0) out[t * BSZ + b] = osc * un;

        float y = s_y[t];
        unsigned yb = __float_as_uint(y);
        float y_ = ((yb & 0x7FFFFFFFu) > 0x7F800000u) ? un : y;   // NaN-safe under fast-math
        ylp = fmaf(cty, ylp, y_ * ity);
        float en = ylp - un;
        elp = fmaf(cte, elp, en * ite);
        float lr = lr0 * lrmult;
        float le = lr * elp;
        float nrm = sqrtf(fmaf(le * le, h2, FUDGE_C));   // ||dw|| with fudge
        lrmult *= expf(-lrd * nrm);

        // Precompute next step's inputs (carry in registers).
        int tn = (t + 1 < T_STEPS) ? (t + 1) : t;
        qlp = fmaf(ctq, qlp, s_q[tn] * itq);
        x   = fmaf(ufs, un, en + s_n[tn]);
        cq  = qsc * qlp;
        lrelp = le;
        wdec  = fmaf(-lr, spwd, 1.0f);
    }
}

extern "C" void kernel_launch(void* const* d_in, const int* in_sizes, int n_in,
                              void* d_out, int out_size)
{
    // metadata order: n, noises, ys, qs, z_biases, w_in, w_inq,
    // log_learning_rate, log_learning_rate_decay, sigma_b, output_scale,
    // u_feedback_scale, sp_weight_decay, q_scale, tauqlpf_m1, tauylpf_m1, tauelpf_m1
    const float* noises = (const float*)d_in[1];
    const float* ys     = (const float*)d_in[2];
    const float* qs     = (const float*)d_in[3];
    const float* zb     = (const float*)d_in[4];
    const float* w_in   = (const float*)d_in[5];
    const float* w_inq  = (const float*)d_in[6];
    const float* p_llr  = (const float*)d_in[7];
    const float* p_llrd = (const float*)d_in[8];
    const float* p_sigb = (const float*)d_in[9];
    const float* p_os   = (const float*)d_in[10];
    const float* p_ufs  = (const float*)d_in[11];
    const float* p_spwd = (const float*)d_in[12];
    const float* p_qsc  = (const float*)d_in[13];
    const float* p_tq   = (const float*)d_in[14];
    const float* p_ty   = (const float*)d_in[15];
    const float* p_te   = (const float*)d_in[16];

    elbo_scan_kernel<<<BSZ, BLOCK>>>(noises, ys, qs, zb, w_in, w_inq,
                                     p_llr, p_llrd, p_sigb, p_os, p_ufs,
                                     p_spwd, p_qsc, p_tq, p_ty, p_te,
                                     (float*)d_out);
}

// round 2
// speedup vs baseline: 1.1661x; 1.1661x over previous
#include <cuda_runtime.h>
#include <cuda_bf16.h>

// T=256, BS=128, N=2048. One persistent CTA per batch lane.
#define T_STEPS 256
#define BSZ     128
#define NFEAT   2048
#define BLOCK   128
#define EPT     16                 // elements per thread
#define PAIRS   (EPT / 2)          // 8 packed f32x2 pairs
#define NWARP   (BLOCK / 32)       // 4 warps
#define FUDGE_C 1e-4f

typedef unsigned long long ull;

static __device__ __forceinline__ ull pack2(float lo, float hi) {
    ull r; asm("mov.b64 %0, {%1, %2};" : "=l"(r) : "f"(lo), "f"(hi)); return r;
}
static __device__ __forceinline__ ull bcast2(float v) { return pack2(v, v); }
static __device__ __forceinline__ float2 unpack2(ull v) {
    float2 r; asm("mov.b64 {%0, %1}, %2;" : "=f"(r.x), "=f"(r.y) : "l"(v)); return r;
}
static __device__ __forceinline__ ull fma2(ull a, ull b, ull c) {
    ull d; asm("fma.rn.f32x2 %0, %1, %2, %3;" : "=l"(d) : "l"(a), "l"(b), "l"(c)); return d;
}
static __device__ __forceinline__ ull add2(ull a, ull b) {
    ull d; asm("add.rn.f32x2 %0, %1, %2;" : "=l"(d) : "l"(a), "l"(b)); return d;
}
static __device__ __forceinline__ ull relu2(ull v) {
    float2 f = unpack2(v);
    return pack2(fmaxf(f.x, 0.0f), fmaxf(f.y, 0.0f));
}

__global__ __launch_bounds__(BLOCK, 1)
void elbo_scan_kernel(const float* __restrict__ noises,   // [T,BS]
                      const float* __restrict__ ys,       // [T,BS]
                      const float* __restrict__ qs,       // [T,BS]
                      const float* __restrict__ z_biases, // [N]
                      const float* __restrict__ w_in,     // [N]
                      const float* __restrict__ w_inq,    // [N]
                      const float* __restrict__ p_llr,
                      const float* __restrict__ p_llrd,
                      const float* __restrict__ p_sigb,
                      const float* __restrict__ p_os,
                      const float* __restrict__ p_ufs,
                      const float* __restrict__ p_spwd,
                      const float* __restrict__ p_qsc,
                      const float* __restrict__ p_tq,
                      const float* __restrict__ p_ty,
                      const float* __restrict__ p_te,
                      float* __restrict__ out)            // [T,BS]
{
    const int b    = blockIdx.x;
    const int tid  = threadIdx.x;
    const int wid  = tid >> 5;
    const int lane = tid & 31;

    __shared__ float  s_y[T_STEPS];
    __shared__ float  s_n[T_STEPS];
    __shared__ float  s_q[T_STEPS];
    __shared__ float2 s_p[2][2 * NWARP];   // double-buffered (dot, h2) partials

    // Stage this lane's input columns (one time).
    s_y[tid]           = ys[tid * BSZ + b];
    s_y[tid + BLOCK]   = ys[(tid + BLOCK) * BSZ + b];
    s_n[tid]           = noises[tid * BSZ + b];
    s_n[tid + BLOCK]   = noises[(tid + BLOCK) * BSZ + b];
    s_q[tid]           = qs[tid * BSZ + b];
    s_q[tid + BLOCK]   = qs[(tid + BLOCK) * BSZ + b];

    // Derived scalar parameters.
    const float lr0   = expf(p_llr[0]);
    const float lrd   = expf(p_llrd[0]);
    const float sigb  = p_sigb[0];
    const float osc   = p_os[0];
    const float ufsm1 = p_ufs[0] - 1.0f;                 // x = (ufs-1)*u + ylp + n
    const float spwd  = log1pf(expf(p_spwd[0]));
    const float qsc   = p_qsc[0];
    const float tq    = 1.0f + log1pf(expf(p_tq[0]));
    const float ty    = 1.0f + log1pf(expf(p_ty[0]));
    const float te    = 1.0f + log1pf(expf(p_te[0]));
    const float itq = 1.0f / tq, ctq = 1.0f - itq;
    const float ity = 1.0f / ty, cty = 1.0f - ity;
    const float ite = 1.0f / te, cte = 1.0f - ite;

    // Register-resident per-thread slices, packed f32x2.
    ull win2[PAIRS], wiq2[PAIRS], bia2[PAIRS], W2[PAIRS], h2v[PAIRS];
    {
        const int base = tid * EPT;
        const float4* w4 = reinterpret_cast<const float4*>(w_in + base);
        const float4* q4 = reinterpret_cast<const float4*>(w_inq + base);
        const float4* z4 = reinterpret_cast<const float4*>(z_biases + base);
        #pragma unroll
        for (int v = 0; v < EPT / 4; ++v) {
            float4 a = w4[v], c = q4[v], z = z4[v];
            win2[2*v]   = pack2(a.x, a.y);  win2[2*v+1] = pack2(a.z, a.w);
            wiq2[2*v]   = pack2(c.x, c.y);  wiq2[2*v+1] = pack2(c.z, c.w);
            bia2[2*v]   = pack2(sigb * z.x, sigb * z.y);
            bia2[2*v+1] = pack2(sigb * z.z, sigb * z.w);
        }
    }
    #pragma unroll
    for (int k = 0; k < PAIRS; ++k) { W2[k] = 0ull; h2v[k] = 0ull; }

    __syncthreads();

    // Replicated scalar state (deterministic in every thread).
    float lrmult = 1.0f, ylp = 0.0f, elp = 0.0f;
    float cW = 1.0f;                       // w_out = cW * W (folded weight decay)
    float qlp = s_q[0] * itq;
    ull   x2   = bcast2(s_n[0]);           // x_0 = noise_0
    ull   cq2  = bcast2(qsc * qlp);
    ull   leoc2 = bcast2(0.0f);            // deferred weight-update coeff

    for (int t = 0; t < T_STEPS; ++t) {
        // --- Phase 1: deferred W update, h_t, dot(W,h), sum(h^2). ---
        ull au0 = 0ull, au1 = 0ull, ah0 = 0ull, ah1 = 0ull;
        #pragma unroll
        for (int k = 0; k < PAIRS; ++k) {
            W2[k] = fma2(leoc2, h2v[k], W2[k]);            // uses OLD h (t-1)
            ull hv = fma2(win2[k], x2, fma2(wiq2[k], cq2, bia2[k]));
            hv = relu2(hv);
            if (k & 1) { au1 = fma2(W2[k], hv, au1); ah1 = fma2(hv, hv, ah1); }
            else       { au0 = fma2(W2[k], hv, au0); ah0 = fma2(hv, hv, ah0); }
            h2v[k] = hv;
        }
        float2 auf = unpack2(add2(au0, au1));
        float2 ahf = unpack2(add2(ah0, ah1));
        float au_s = auf.x + auf.y;
        float ah_s = ahf.x + ahf.y;

        // --- 4-level butterfly: lanes 0/1 end with the two half-sums. ---
        #pragma unroll
        for (int off = 16; off >= 2; off >>= 1) {
            au_s += __shfl_xor_sync(0xFFFFFFFFu, au_s, off);
            ah_s += __shfl_xor_sync(0xFFFFFFFFu, ah_s, off);
        }
        const int buf = t & 1;
        if (lane < 2) s_p[buf][(wid << 1) | lane] = make_float2(au_s, ah_s);

        // --- Off-critical-path precompute (before the barrier). ---
        const float y  = s_y[t];
        const bool flag = ((__float_as_uint(y) & 0x7FFFFFFFu) > 0x7F800000u); // isnan
        const float byl = cty * ylp;
        const int  tn   = (t + 1 < T_STEPS) ? (t + 1) : t;
        const float bylpn = byl + s_n[tn];            // cty*ylp + noise_{t+1}
        const float qn    = s_q[tn] * itq;

        __syncthreads();                              // the only barrier per step

        // --- Redundant combine (broadcast LDS, no conflicts). ---
        float2 c0 = s_p[buf][0], c1 = s_p[buf][1], c2 = s_p[buf][2], c3 = s_p[buf][3];
        float2 c4 = s_p[buf][4], c5 = s_p[buf][5], c6 = s_p[buf][6], c7 = s_p[buf][7];
        float sumu = ((c0.x + c1.x) + (c2.x + c3.x)) + ((c4.x + c5.x) + (c6.x + c7.x));
        float sumh = ((c0.y + c1.y) + (c2.y + c3.y)) + ((c4.y + c5.y) + (c6.y + c7.y));

        const float un   = cW * sumu;                 // u_t
        const float ysel = flag ? un : y;
        // Critical path to next elementwise: SEL -> FMA -> FMA.
        const float xn = fmaf(ufsm1, un, fmaf(ity, ysel, bylpn));
        x2 = bcast2(xn);

        if (tid == 0) out[t * BSZ + b] = osc * un;

        // Trailing scalar chain (gates only the W-update half of next loop).
        const float ylpn = fmaf(ity, ysel, byl);
        const float en   = ylpn - un;
        ylp = ylpn;
        elp = fmaf(cte, elp, en * ite);
        const float lr = lr0 * lrmult;
        const float le = lr * elp;
        const float v  = fmaf(le * le, sumh, FUDGE_C);
        const float nrm = v * __frsqrt_rn(v);         // sqrt(v), v >= 1e-4
        lrmult *= __expf(-lrd * nrm);
        const float wdec = fmaf(-lr, spwd, 1.0f);
        cW *= wdec;                                   // fold decay into scale
        leoc2 = bcast2(__fdividef(le, cW));
        qlp = fmaf(ctq, qlp, qn);
        cq2 = bcast2(qsc * qlp);
    }
}

extern "C" void kernel_launch(void* const* d_in, const int* in_sizes, int n_in,
                              void* d_out, int out_size)
{
    const float* noises = (const float*)d_in[1];
    const float* ys     = (const float*)d_in[2];
    const float* qs     = (const float*)d_in[3];
    const float* zb     = (const float*)d_in[4];
    const float* w_in   = (const float*)d_in[5];
    const float* w_inq  = (const float*)d_in[6];

    elbo_scan_kernel<<<BSZ, BLOCK>>>(noises, ys, qs, zb, w_in, w_inq,
                                     (const float*)d_in[7],  (const float*)d_in[8],
                                     (const float*)d_in[9],  (const float*)d_in[10],
                                     (const float*)d_in[11], (const float*)d_in[12],
                                     (const float*)d_in[13], (const float*)d_in[14],
                                     (const float*)d_in[15], (const float*)d_in[16],
                                     (float*)d_out);
}

// round 4
// speedup vs baseline: 1.1750x; 1.0076x over previous
#include <cuda_runtime.h>
#include <cuda_bf16.h>

// T=256, BS=128, N=2048. One persistent CTA per batch lane.
#define T_STEPS 256
#define BSZ     128
#define NFEAT   2048
#define BLOCK   128
#define EPT     16                 // elements per thread
#define PAIRS   (EPT / 2)          // 8 packed f32x2 pairs
#define NWARP   (BLOCK / 32)       // 4 warps
#define FUDGE_C 1e-4f

typedef unsigned long long ull;

static __device__ __forceinline__ ull pack2(float lo, float hi) {
    ull r; asm("mov.b64 %0, {%1, %2};" : "=l"(r) : "f"(lo), "f"(hi)); return r;
}
static __device__ __forceinline__ ull bcast2(float v) { return pack2(v, v); }
static __device__ __forceinline__ float2 unpack2(ull v) {
    float2 r; asm("mov.b64 {%0, %1}, %2;" : "=f"(r.x), "=f"(r.y) : "l"(v)); return r;
}
static __device__ __forceinline__ ull fma2(ull a, ull b, ull c) {
    ull d; asm("fma.rn.f32x2 %0, %1, %2, %3;" : "=l"(d) : "l"(a), "l"(b), "l"(c)); return d;
}
static __device__ __forceinline__ ull add2(ull a, ull b) {
    ull d; asm("add.rn.f32x2 %0, %1, %2;" : "=l"(d) : "l"(a), "l"(b)); return d;
}
static __device__ __forceinline__ ull relu2(ull v) {
    float2 f = unpack2(v);
    return pack2(fmaxf(f.x, 0.0f), fmaxf(f.y, 0.0f));
}

__global__ __launch_bounds__(BLOCK, 1)
void elbo_scan_kernel(const float* __restrict__ noises,   // [T,BS]
                      const float* __restrict__ ys,       // [T,BS]
                      const float* __restrict__ qs,       // [T,BS]
                      const float* __restrict__ z_biases, // [N]
                      const float* __restrict__ w_in,     // [N]
                      const float* __restrict__ w_inq,    // [N]
                      const float* __restrict__ p_llr,
                      const float* __restrict__ p_llrd,
                      const float* __restrict__ p_sigb,
                      const float* __restrict__ p_os,
                      const float* __restrict__ p_ufs,
                      const float* __restrict__ p_spwd,
                      const float* __restrict__ p_qsc,
                      const float* __restrict__ p_tq,
                      const float* __restrict__ p_ty,
                      const float* __restrict__ p_te,
                      float* __restrict__ out)            // [T,BS]
{
    const int b    = blockIdx.x;
    const int tid  = threadIdx.x;
    const int wid  = tid >> 5;
    const int lane = tid & 31;

    __shared__ float  s_y[T_STEPS];
    __shared__ float  s_n[T_STEPS];
    __shared__ float  s_q[T_STEPS];
    __shared__ float2 s_p[2][2 * NWARP];   // double-buffered per-warp parity halves

    // Stage this lane's input columns (one time).
    s_y[tid]         = ys[tid * BSZ + b];
    s_y[tid + BLOCK] = ys[(tid + BLOCK) * BSZ + b];
    s_n[tid]         = noises[tid * BSZ + b];
    s_n[tid + BLOCK] = noises[(tid + BLOCK) * BSZ + b];
    s_q[tid]         = qs[tid * BSZ + b];
    s_q[tid + BLOCK] = qs[(tid + BLOCK) * BSZ + b];

    // Derived scalar parameters.
    const float lr0   = expf(p_llr[0]);
    const float lrd   = expf(p_llrd[0]);
    const float sigb  = p_sigb[0];
    const float osc   = p_os[0];
    const float ufsm1 = p_ufs[0] - 1.0f;
    const float spwd  = log1pf(expf(p_spwd[0]));
    const float qsc   = p_qsc[0];
    const float tq    = 1.0f + log1pf(expf(p_tq[0]));
    const float ty    = 1.0f + log1pf(expf(p_ty[0]));
    const float te    = 1.0f + log1pf(expf(p_te[0]));
    const float itq = 1.0f / tq, ctq = 1.0f - itq;
    const float ity = 1.0f / ty, cty = 1.0f - ity;
    const float ite = 1.0f / te, cte = 1.0f - ite;

    // Register-resident per-thread slices, packed f32x2.
    ull win2[PAIRS], wiq2[PAIRS], bia2[PAIRS], W2[PAIRS], A2[PAIRS];
    {
        const int base = tid * EPT;
        const float4* w4 = reinterpret_cast<const float4*>(w_in + base);
        const float4* q4 = reinterpret_cast<const float4*>(w_inq + base);
        const float4* z4 = reinterpret_cast<const float4*>(z_biases + base);
        #pragma unroll
        for (int v = 0; v < EPT / 4; ++v) {
            float4 a = w4[v], c = q4[v], z = z4[v];
            win2[2*v]   = pack2(a.x, a.y);  win2[2*v+1] = pack2(a.z, a.w);
            wiq2[2*v]   = pack2(c.x, c.y);  wiq2[2*v+1] = pack2(c.z, c.w);
            bia2[2*v]   = pack2(sigb * z.x, sigb * z.y);
            bia2[2*v+1] = pack2(sigb * z.z, sigb * z.w);
        }
    }
    #pragma unroll
    for (int k = 0; k < PAIRS; ++k) W2[k] = 0ull;

    __syncthreads();

    // Replicated scalar state (identical deterministic values in every thread).
    float lrmult = 1.0f, ylp = 0.0f, elp = 0.0f, cW = 1.0f;
    float qlp = s_q[0] * itq;
    {   // A for step 0
        const ull cq2 = bcast2(qsc * qlp);
        #pragma unroll
        for (int k = 0; k < PAIRS; ++k) A2[k] = fma2(cq2, wiq2[k], bia2[k]);
    }
    ull x2 = bcast2(s_n[0]);               // x_0 = noise_0 (u=0, e=0)

    for (int t = 0; t < T_STEPS; ++t) {
        // --- Elementwise: h_t, dot(W,h), sum(h^2). W is already W_t. ---
        ull hv[PAIRS];
        ull au0 = 0ull, au1 = 0ull, ah0 = 0ull, ah1 = 0ull;
        #pragma unroll
        for (int k = 0; k < PAIRS; ++k) {
            ull h = relu2(fma2(win2[k], x2, A2[k]));
            hv[k] = h;
            if (k & 1) { au1 = fma2(W2[k], h, au1); ah1 = fma2(h, h, ah1); }
            else       { au0 = fma2(W2[k], h, au0); ah0 = fma2(h, h, ah0); }
        }
        float2 auf = unpack2(add2(au0, au1));
        float2 ahf = unpack2(add2(ah0, ah1));
        float au_s = auf.x + auf.y;
        float ah_s = ahf.x + ahf.y;

        // --- 4-level butterfly (two interleaved chains); lanes 0/1 hold parity halves. ---
        #pragma unroll
        for (int off = 16; off >= 2; off >>= 1) {
            au_s += __shfl_xor_sync(0xFFFFFFFFu, au_s, off);
            ah_s += __shfl_xor_sync(0xFFFFFFFFu, ah_s, off);
        }
        const int buf = t & 1;
        if (lane < 2) s_p[buf][(wid << 1) | lane] = make_float2(au_s, ah_s);

        // --- Latency-shadow prep for step t+1 (independent of the reduction). ---
        const int  tn   = (t + 1 < T_STEPS) ? (t + 1) : t;
        const float y   = s_y[t];
        const bool flag = ((__float_as_uint(y) & 0x7FFFFFFFu) > 0x7F800000u); // isnan
        const float byl = cty * ylp;
        const float ax  = ufsm1 + (flag ? ity : 0.0f);                // x_{t+1} = ax*u_t + bx
        const float bx  = (flag ? 0.0f : ity * y) + byl + s_n[tn];
        qlp = fmaf(ctq, qlp, s_q[tn] * itq);
        const ull cq2 = bcast2(qsc * qlp);
        #pragma unroll
        for (int k = 0; k < PAIRS; ++k) A2[k] = fma2(cq2, wiq2[k], bia2[k]);

        __syncthreads();                    // the only barrier per step

        // --- Redundant combine: 8 broadcast LDS float2, short add tree. ---
        float2 c0 = s_p[buf][0], c1 = s_p[buf][1], c2 = s_p[buf][2], c3 = s_p[buf][3];
        float2 c4 = s_p[buf][4], c5 = s_p[buf][5], c6 = s_p[buf][6], c7 = s_p[buf][7];
        const float sumu = ((c0.x + c1.x) + (c2.x + c3.x)) + ((c4.x + c5.x) + (c6.x + c7.x));
        const float sumh = ((c0.y + c1.y) + (c2.y + c3.y)) + ((c4.y + c5.y) + (c6.y + c7.y));

        const float un = cW * sumu;                         // u_t
        x2 = bcast2(fmaf(ax, un, bx));                      // x_{t+1}: 1 FMA off un

        if (tid == 0) out[t * BSZ + b] = osc * un;

        // --- Trailing scalar chain (gates only the W update below). ---
        const float ysel = flag ? un : y;
        const float ylpn = fmaf(ity, ysel, byl);
        const float en   = ylpn - un;
        ylp = ylpn;
        elp = fmaf(cte, elp, en * ite);
        const float lr = lr0 * lrmult;
        const float le = lr * elp;
        const float v  = fmaf(le * le, sumh, FUDGE_C);
        lrmult *= __expf(-lrd * (v * __frsqrt_rn(v)));      // exp(-lrd*sqrt(v))
        cW *= fmaf(-lr, spwd, 1.0f);                        // folded weight decay
        const ull leoc2 = bcast2(__fdividef(le, cW));

        // --- Deferred W update with h_t still live in registers. ---
        #pragma unroll
        for (int k = 0; k < PAIRS; ++k) W2[k] = fma2(leoc2, hv[k], W2[k]);
    }
}

extern "C" void kernel_launch(void* const* d_in, const int* in_sizes, int n_in,
                              void* d_out, int out_size)
{
    const float* noises = (const float*)d_in[1];
    const float* ys     = (const float*)d_in[2];
    const float* qs     = (const float*)d_in[3];
    const float* zb     = (const float*)d_in[4];
    const float* w_in   = (const float*)d_in[5];
    const float* w_inq  = (const float*)d_in[6];

    elbo_scan_kernel<<<BSZ, BLOCK>>>(noises, ys, qs, zb, w_in, w_inq,
                                     (const float*)d_in[7],  (const float*)d_in[8],
                                     (const float*)d_in[9],  (const float*)d_in[10],
                                     (const float*)d_in[11], (const float*)d_in[12],
                                     (const float*)d_in[13], (const float*)d_in[14],
                                     (const float*)d_in[15], (const float*)d_in[16],
                                     (float*)d_out);
}